// round 1
// baseline (speedup 1.0000x reference)
#include <cuda_runtime.h>
#include <math.h>

// Problem constants (shapes fixed by the reference setup)
#define LSEQ 256
#define EDIM 768
#define HDIM 384
#define NDOM 9
#define BMAX 2048

// Device scratch (no cudaMalloc allowed)
__device__ float g_feature[(size_t)BMAX * EDIM];  // [B, 2H] = [B, 768] : [shared | specific]
__device__ float g_h1[(size_t)BMAX * 64];
__device__ int   g_counts[16];
__device__ int   g_idx[NDOM * BMAX];

// ---------------------------------------------------------------------------
// K1: fused masked-attention pooling with online softmax.
// One CTA per sample, 192 threads, float4 per thread (192*4 = 768 = E).
// Reads bert_feature exactly once (1.61 GB total) -> memory-bound floor.
// ---------------------------------------------------------------------------
__global__ void __launch_bounds__(192) pool_kernel(
    const float* __restrict__ bert, const int* __restrict__ masks,
    const float* __restrict__ att_w, const float* __restrict__ att_b,
    float* __restrict__ pooled)
{
    const int b = blockIdx.x;
    const int tid = threadIdx.x;           // 0..191
    const int nv = EDIM / 4;               // 192 float4 per token
    const float4* base = reinterpret_cast<const float4*>(bert + (size_t)b * LSEQ * EDIM);
    const float4 w = reinterpret_cast<const float4*>(att_w)[tid];
    const int* mrow = masks + b * LSEQ;
    const float bb = att_b[0];

    __shared__ float wr[2][6];

    float4 acc = make_float4(0.f, 0.f, 0.f, 0.f);
    float m = -3e38f, d = 0.f;

    float4 x = base[tid];  // prefetch token 0
    for (int l = 0; l < LSEQ; ++l) {
        // partial dot for score
        float p = x.x * w.x + x.y * w.y + x.z * w.z + x.w * w.w;
        // prefetch next token early (overlaps the reduce + barrier)
        float4 xn;
        if (l + 1 < LSEQ) xn = base[(l + 1) * nv + tid];
        // warp reduce
        #pragma unroll
        for (int o = 16; o; o >>= 1) p += __shfl_xor_sync(0xffffffffu, p, o);
        if ((tid & 31) == 0) wr[l & 1][tid >> 5] = p;
        __syncthreads();
        float s = wr[l & 1][0] + wr[l & 1][1] + wr[l & 1][2] +
                  wr[l & 1][3] + wr[l & 1][4] + wr[l & 1][5] + bb;
        if (mrow[l] == 0) s = -1e9f;

        // online softmax update
        float nm = fmaxf(m, s);
        float f  = __expf(m - nm);
        float pe = __expf(s - nm);
        d = d * f + pe;
        acc.x = acc.x * f + pe * x.x;
        acc.y = acc.y * f + pe * x.y;
        acc.z = acc.z * f + pe * x.z;
        acc.w = acc.w * f + pe * x.w;
        m = nm;
        x = xn;
    }
    const float inv = 1.f / d;
    float4 o = make_float4(acc.x * inv, acc.y * inv, acc.z * inv, acc.w * inv);
    reinterpret_cast<float4*>(pooled + (size_t)b * EDIM)[tid] = o;
}

// ---------------------------------------------------------------------------
// K2: per-category index lists (so the routed expert becomes 9 dense GEMMs)
// ---------------------------------------------------------------------------
__global__ void zero_counts_kernel() {
    if (threadIdx.x < 16) g_counts[threadIdx.x] = 0;
}

__global__ void scatter_kernel(const int* __restrict__ category, int B) {
    int i = blockIdx.x * blockDim.x + threadIdx.x;
    if (i < B) {
        int c = category[i];
        int p = atomicAdd(&g_counts[c], 1);
        g_idx[c * BMAX + p] = i;
    }
}

// ---------------------------------------------------------------------------
// K3: expert GEMM with row gather. blockIdx.z = category (9 == shared MLP).
// Tile 64x64, K-step 16, 256 threads, 4x4 micro-tile per thread.
// Output: shared -> g_feature[:, 0:384], specific -> g_feature[:, 384:768].
// ---------------------------------------------------------------------------
__global__ void __launch_bounds__(256) expert_gemm_kernel(
    const float* __restrict__ pooled,
    const float* __restrict__ Wsh, const float* __restrict__ bsh,
    const float* __restrict__ Wsp, const float* __restrict__ bsp,
    int B)
{
    const int c  = blockIdx.z;   // 0..8 specific, 9 shared
    const int mt = blockIdx.y;
    const int nt = blockIdx.x;   // 0..5 (384/64)
    const int cnt = (c == 9) ? B : g_counts[c];
    if (mt * 64 >= cnt) return;

    const float* W    = (c == 9) ? Wsh : (Wsp + (size_t)c * EDIM * HDIM);
    const float* bias = (c == 9) ? bsh : (bsp + c * HDIM);
    const int colbase = nt * 64;
    const int outcol  = ((c == 9) ? 0 : HDIM) + colbase;

    __shared__ float As[16][68];   // padded, rows remain 16B-aligned (68*4=272=16*17)
    __shared__ float Bs[16][64];

    const int t = threadIdx.x;
    const int arow = t >> 2, akk = (t & 3) * 4;   // A-load mapping
    const int bk   = t >> 4, bn  = (t & 15) * 4;  // B-load mapping
    const int ty = t >> 4, tx = t & 15;           // compute mapping

    // resolve gathered sample index for this thread's A-load row
    int gidx = -1;
    {
        int amrow = mt * 64 + arow;
        if (amrow < cnt) gidx = (c == 9) ? amrow : g_idx[c * BMAX + amrow];
    }

    float accv[4][4];
    #pragma unroll
    for (int i = 0; i < 4; ++i)
        #pragma unroll
        for (int j = 0; j < 4; ++j) accv[i][j] = 0.f;

    for (int k0 = 0; k0 < EDIM; k0 += 16) {
        float4 av = make_float4(0.f, 0.f, 0.f, 0.f);
        if (gidx >= 0)
            av = *reinterpret_cast<const float4*>(pooled + (size_t)gidx * EDIM + k0 + akk);
        float4 bv = *reinterpret_cast<const float4*>(W + (size_t)(k0 + bk) * HDIM + colbase + bn);

        __syncthreads();  // protect previous iteration's reads
        As[akk + 0][arow] = av.x;
        As[akk + 1][arow] = av.y;
        As[akk + 2][arow] = av.z;
        As[akk + 3][arow] = av.w;
        *reinterpret_cast<float4*>(&Bs[bk][bn]) = bv;
        __syncthreads();

        #pragma unroll
        for (int kk = 0; kk < 16; ++kk) {
            float4 a = *reinterpret_cast<const float4*>(&As[kk][ty * 4]);
            float4 bq = *reinterpret_cast<const float4*>(&Bs[kk][tx * 4]);
            float ar[4] = {a.x, a.y, a.z, a.w};
            float br[4] = {bq.x, bq.y, bq.z, bq.w};
            #pragma unroll
            for (int i = 0; i < 4; ++i)
                #pragma unroll
                for (int j = 0; j < 4; ++j)
                    accv[i][j] += ar[i] * br[j];
        }
    }

    // bias + ReLU + gathered store
    float4 bvec = *reinterpret_cast<const float4*>(bias + colbase + tx * 4);
    float bb[4] = {bvec.x, bvec.y, bvec.z, bvec.w};
    #pragma unroll
    for (int i = 0; i < 4; ++i) {
        int grow = mt * 64 + ty * 4 + i;
        if (grow < cnt) {
            int ridx = (c == 9) ? grow : g_idx[c * BMAX + grow];
            float4 ov;
            ov.x = fmaxf(accv[i][0] + bb[0], 0.f);
            ov.y = fmaxf(accv[i][1] + bb[1], 0.f);
            ov.z = fmaxf(accv[i][2] + bb[2], 0.f);
            ov.w = fmaxf(accv[i][3] + bb[3], 0.f);
            *reinterpret_cast<float4*>(&g_feature[(size_t)ridx * EDIM + outcol + tx * 4]) = ov;
        }
    }
}

// ---------------------------------------------------------------------------
// K4: decoder stage 1 (feature @ Wd1 + relu -> h1[64]) + classifier head.
// One block of 128 threads per sample; feature row cached in smem.
// ---------------------------------------------------------------------------
__global__ void __launch_bounds__(128) dec1_cls_kernel(
    const float* __restrict__ Wd1, const float* __restrict__ bd1,
    const float* __restrict__ Wc, const float* __restrict__ bc,
    float* __restrict__ out)
{
    const int b = blockIdx.x;
    const int t = threadIdx.x;
    __shared__ float f[EDIM];
    __shared__ float cred[2];

    for (int i = t; i < EDIM; i += 128) f[i] = g_feature[(size_t)b * EDIM + i];
    __syncthreads();

    float acc = 0.f;
    if (t < 64) {
        #pragma unroll 8
        for (int k = 0; k < EDIM; ++k) acc += f[k] * Wd1[k * 64 + t];
    } else {
        const int u = t - 64;
        for (int k = u; k < EDIM; k += 64) acc += f[k] * Wc[k];
        #pragma unroll
        for (int o = 16; o; o >>= 1) acc += __shfl_xor_sync(0xffffffffu, acc, o);
        if ((t & 31) == 0) cred[(t >> 5) - 2] = acc;
    }
    __syncthreads();
    if (t < 64) g_h1[b * 64 + t] = fmaxf(acc + bd1[t], 0.f);
    if (t == 64) {
        float z = cred[0] + cred[1] + bc[0];
        out[b] = 1.f / (1.f + __expf(-z));
    }
}

// ---------------------------------------------------------------------------
// K5: decoder stage 2 (h1 @ Wd2 + relu -> rec[768])
// ---------------------------------------------------------------------------
__global__ void __launch_bounds__(256) dec2_kernel(
    const float* __restrict__ Wd2, const float* __restrict__ bd2,
    float* __restrict__ rec)
{
    const int b = blockIdx.x;
    const int t = threadIdx.x;
    __shared__ float h[64];
    if (t < 64) h[t] = g_h1[b * 64 + t];
    __syncthreads();

    float a0 = 0.f, a1 = 0.f, a2 = 0.f;
    #pragma unroll 8
    for (int k = 0; k < 64; ++k) {
        float hk = h[k];
        const float* wrow = Wd2 + (size_t)k * EDIM;
        a0 += hk * wrow[t];
        a1 += hk * wrow[t + 256];
        a2 += hk * wrow[t + 512];
    }
    float* r = rec + (size_t)b * EDIM;
    r[t]       = fmaxf(a0 + bd2[t], 0.f);
    r[t + 256] = fmaxf(a1 + bd2[t + 256], 0.f);
    r[t + 512] = fmaxf(a2 + bd2[t + 512], 0.f);
}

// ---------------------------------------------------------------------------
// K6: domain classifier: h = relu(shared @ Wdo1 + bdo1); dp = h @ Wdo2 + bdo2
// ---------------------------------------------------------------------------
__global__ void __launch_bounds__(384) domain_kernel(
    const float* __restrict__ Wdo1, const float* __restrict__ bdo1,
    const float* __restrict__ Wdo2, const float* __restrict__ bdo2,
    float* __restrict__ dp)
{
    const int b = blockIdx.x;
    const int t = threadIdx.x;  // 0..383
    __shared__ float sh[HDIM];
    __shared__ float hd[HDIM];

    sh[t] = g_feature[(size_t)b * EDIM + t];  // shared part = cols [0, 384)
    __syncthreads();

    float acc = 0.f;
    #pragma unroll 4
    for (int k = 0; k < HDIM; ++k) acc += sh[k] * Wdo1[k * HDIM + t];
    hd[t] = fmaxf(acc + bdo1[t], 0.f);
    __syncthreads();

    if (t < NDOM) {
        float a = 0.f;
        for (int k = 0; k < HDIM; ++k) a += hd[k] * Wdo2[k * NDOM + t];
        dp[(size_t)b * NDOM + t] = a + bdo2[t];
    }
}

// ---------------------------------------------------------------------------
// launch
// ---------------------------------------------------------------------------
extern "C" void kernel_launch(void* const* d_in, const int* in_sizes, int n_in,
                              void* d_out, int out_size)
{
    const float* bert     = (const float*)d_in[0];
    const int*   masks    = (const int*)d_in[1];
    const int*   category = (const int*)d_in[2];
    // d_in[3] = alpha (identity in forward)
    const float* att_w = (const float*)d_in[4];
    const float* att_b = (const float*)d_in[5];
    const float* Wsh = (const float*)d_in[6];  const float* bsh = (const float*)d_in[7];
    const float* Wsp = (const float*)d_in[8];  const float* bsp = (const float*)d_in[9];
    const float* Wd1 = (const float*)d_in[10]; const float* bd1 = (const float*)d_in[11];
    const float* Wd2 = (const float*)d_in[12]; const float* bd2 = (const float*)d_in[13];
    const float* Wc  = (const float*)d_in[14]; const float* bc  = (const float*)d_in[15];
    const float* Wdo1 = (const float*)d_in[16]; const float* bdo1 = (const float*)d_in[17];
    const float* Wdo2 = (const float*)d_in[18]; const float* bdo2 = (const float*)d_in[19];

    const int B = in_sizes[2];  // category has one entry per sample

    // output tuple layout: out [B], rec [B,E], pooled [B,E], domain_pred [B,9]
    float* out    = (float*)d_out;
    float* rec    = out + B;
    float* pooled = rec + (size_t)B * EDIM;
    float* dp     = pooled + (size_t)B * EDIM;

    pool_kernel<<<B, 192>>>(bert, masks, att_w, att_b, pooled);

    zero_counts_kernel<<<1, 16>>>();
    scatter_kernel<<<(B + 255) / 256, 256>>>(category, B);

    dim3 g3(HDIM / 64, (B + 63) / 64, NDOM + 1);
    expert_gemm_kernel<<<g3, 256>>>(pooled, Wsh, bsh, Wsp, bsp, B);

    dec1_cls_kernel<<<B, 128>>>(Wd1, bd1, Wc, bc, out);
    dec2_kernel<<<B, 256>>>(Wd2, bd2, rec);
    domain_kernel<<<B, 384>>>(Wdo1, bdo1, Wdo2, bdo2, dp);
}

// round 4
// speedup vs baseline: 1.0610x; 1.0610x over previous
#include <cuda_runtime.h>
#include <math.h>

#define LSEQ 256
#define EDIM 768
#define HDIM 384
#define NDOM 9
#define BMAX 2048

// device scratch (no allocation allowed)
__device__ float g_feature[(size_t)BMAX * EDIM];   // [B, 2H]: [shared | specific]
__device__ float g_h1[(size_t)BMAX * 64];
__device__ float g_hdom[(size_t)BMAX * HDIM];
__device__ int   g_counts[16];
__device__ int   g_idx[NDOM * BMAX];

// ---------------------------------------------------------------------------
// K1: fused masked-attention pooling with online softmax (R1-proven version).
// One CTA per sample, 192 threads, float4 per thread. Reads bert once.
// ---------------------------------------------------------------------------
__global__ void __launch_bounds__(192) pool_kernel(
    const float* __restrict__ bert, const int* __restrict__ masks,
    const float* __restrict__ att_w, const float* __restrict__ att_b,
    float* __restrict__ pooled)
{
    const int b = blockIdx.x;
    const int tid = threadIdx.x;           // 0..191
    const int nv = EDIM / 4;               // 192 float4 per token
    const float4* base = reinterpret_cast<const float4*>(bert + (size_t)b * LSEQ * EDIM);
    const float4 w = reinterpret_cast<const float4*>(att_w)[tid];
    const int* mrow = masks + b * LSEQ;
    const float bb = att_b[0];

    __shared__ float wr[2][6];

    float4 acc = make_float4(0.f, 0.f, 0.f, 0.f);
    float m = -3e38f, d = 0.f;

    float4 x = base[tid];  // prefetch token 0
    for (int l = 0; l < LSEQ; ++l) {
        float p = x.x * w.x + x.y * w.y + x.z * w.z + x.w * w.w;
        float4 xn;
        if (l + 1 < LSEQ) xn = base[(l + 1) * nv + tid];
        #pragma unroll
        for (int o = 16; o; o >>= 1) p += __shfl_xor_sync(0xffffffffu, p, o);
        if ((tid & 31) == 0) wr[l & 1][tid >> 5] = p;
        __syncthreads();
        float s = wr[l & 1][0] + wr[l & 1][1] + wr[l & 1][2] +
                  wr[l & 1][3] + wr[l & 1][4] + wr[l & 1][5] + bb;
        if (mrow[l] == 0) s = -1e9f;

        float nm = fmaxf(m, s);
        float f  = __expf(m - nm);
        float pe = __expf(s - nm);
        d = d * f + pe;
        acc.x = acc.x * f + pe * x.x;
        acc.y = acc.y * f + pe * x.y;
        acc.z = acc.z * f + pe * x.z;
        acc.w = acc.w * f + pe * x.w;
        m = nm;
        x = xn;
    }
    const float inv = 1.f / d;
    float4 o = make_float4(acc.x * inv, acc.y * inv, acc.z * inv, acc.w * inv);
    reinterpret_cast<float4*>(pooled + (size_t)b * EDIM)[tid] = o;
}

// ---------------------------------------------------------------------------
// category routing lists
// ---------------------------------------------------------------------------
__global__ void zero_counts_kernel() { if (threadIdx.x < 16) g_counts[threadIdx.x] = 0; }

__global__ void scatter_kernel(const int* __restrict__ category, int B) {
    int i = blockIdx.x * blockDim.x + threadIdx.x;
    if (i < B) {
        int c = category[i];
        int p = atomicAdd(&g_counts[c], 1);
        g_idx[c * BMAX + p] = i;
    }
}

// ---------------------------------------------------------------------------
// Dense tiled GEMM: C = relu(A[M,K] @ W[K,N] + bias). 64x64 tile, K-step 16,
// 256 threads, 4x4 micro-tile. Requires K%16==0, N%64==0.
// ---------------------------------------------------------------------------
__global__ void __launch_bounds__(256) dense_gemm_relu(
    const float* __restrict__ A, int lda,
    const float* __restrict__ W, int ldw,
    const float* __restrict__ bias,
    float* __restrict__ C, int ldc,
    int M, int K)
{
    const int mt = blockIdx.y;
    const int colbase = blockIdx.x * 64;

    __shared__ float As[16][68];
    __shared__ float Bs[16][64];

    const int t = threadIdx.x;
    const int arow = t >> 2, akk = (t & 3) * 4;
    const int bk = t >> 4, bn = (t & 15) * 4;
    const int ty = t >> 4, tx = t & 15;

    const int ga = mt * 64 + arow;
    const bool aload = (ga < M);
    const float* Ap = A + (size_t)(aload ? ga : 0) * lda;

    float accv[4][4];
    #pragma unroll
    for (int i = 0; i < 4; ++i)
        #pragma unroll
        for (int j = 0; j < 4; ++j) accv[i][j] = 0.f;

    for (int k0 = 0; k0 < K; k0 += 16) {
        float4 av = make_float4(0.f, 0.f, 0.f, 0.f);
        if (aload) av = *reinterpret_cast<const float4*>(Ap + k0 + akk);
        float4 bv = *reinterpret_cast<const float4*>(W + (size_t)(k0 + bk) * ldw + colbase + bn);

        __syncthreads();  // protect previous iteration's reads
        As[akk + 0][arow] = av.x;
        As[akk + 1][arow] = av.y;
        As[akk + 2][arow] = av.z;
        As[akk + 3][arow] = av.w;
        *reinterpret_cast<float4*>(&Bs[bk][bn]) = bv;
        __syncthreads();

        #pragma unroll
        for (int kk = 0; kk < 16; ++kk) {
            float4 a4 = *reinterpret_cast<const float4*>(&As[kk][ty * 4]);
            float4 b4 = *reinterpret_cast<const float4*>(&Bs[kk][tx * 4]);
            float ar[4] = {a4.x, a4.y, a4.z, a4.w};
            float br[4] = {b4.x, b4.y, b4.z, b4.w};
            #pragma unroll
            for (int i = 0; i < 4; ++i)
                #pragma unroll
                for (int j = 0; j < 4; ++j)
                    accv[i][j] += ar[i] * br[j];
        }
    }

    float4 bb4 = *reinterpret_cast<const float4*>(bias + colbase + tx * 4);
    float bb[4] = {bb4.x, bb4.y, bb4.z, bb4.w};
    #pragma unroll
    for (int i = 0; i < 4; ++i) {
        const int row = mt * 64 + ty * 4 + i;
        if (row < M) {
            float4 o;
            o.x = fmaxf(accv[i][0] + bb[0], 0.f);
            o.y = fmaxf(accv[i][1] + bb[1], 0.f);
            o.z = fmaxf(accv[i][2] + bb[2], 0.f);
            o.w = fmaxf(accv[i][3] + bb[3], 0.f);
            *reinterpret_cast<float4*>(C + (size_t)row * ldc + colbase + tx * 4) = o;
        }
    }
}

// ---------------------------------------------------------------------------
// Expert GEMM with row gather (R1-proven, specific experts only).
// blockIdx.z = category 0..8. Writes g_feature[:, HDIM:2*HDIM].
// ---------------------------------------------------------------------------
__global__ void __launch_bounds__(256) expert_gemm_kernel(
    const float* __restrict__ pooled,
    const float* __restrict__ Wsp, const float* __restrict__ bsp)
{
    const int c  = blockIdx.z;   // 0..8
    const int mt = blockIdx.y;
    const int nt = blockIdx.x;   // 0..5
    const int cnt = g_counts[c];
    if (mt * 64 >= cnt) return;

    const float* W    = Wsp + (size_t)c * EDIM * HDIM;
    const float* bias = bsp + c * HDIM;
    const int colbase = nt * 64;
    const int outcol  = HDIM + colbase;

    __shared__ float As[16][68];
    __shared__ float Bs[16][64];

    const int t = threadIdx.x;
    const int arow = t >> 2, akk = (t & 3) * 4;
    const int bk   = t >> 4, bn  = (t & 15) * 4;
    const int ty = t >> 4, tx = t & 15;

    int gidx = -1;
    {
        int amrow = mt * 64 + arow;
        if (amrow < cnt) gidx = g_idx[c * BMAX + amrow];
    }

    float accv[4][4];
    #pragma unroll
    for (int i = 0; i < 4; ++i)
        #pragma unroll
        for (int j = 0; j < 4; ++j) accv[i][j] = 0.f;

    for (int k0 = 0; k0 < EDIM; k0 += 16) {
        float4 av = make_float4(0.f, 0.f, 0.f, 0.f);
        if (gidx >= 0)
            av = *reinterpret_cast<const float4*>(pooled + (size_t)gidx * EDIM + k0 + akk);
        float4 bv = *reinterpret_cast<const float4*>(W + (size_t)(k0 + bk) * HDIM + colbase + bn);

        __syncthreads();
        As[akk + 0][arow] = av.x;
        As[akk + 1][arow] = av.y;
        As[akk + 2][arow] = av.z;
        As[akk + 3][arow] = av.w;
        *reinterpret_cast<float4*>(&Bs[bk][bn]) = bv;
        __syncthreads();

        #pragma unroll
        for (int kk = 0; kk < 16; ++kk) {
            float4 a = *reinterpret_cast<const float4*>(&As[kk][ty * 4]);
            float4 bq = *reinterpret_cast<const float4*>(&Bs[kk][tx * 4]);
            float ar[4] = {a.x, a.y, a.z, a.w};
            float br[4] = {bq.x, bq.y, bq.z, bq.w};
            #pragma unroll
            for (int i = 0; i < 4; ++i)
                #pragma unroll
                for (int j = 0; j < 4; ++j)
                    accv[i][j] += ar[i] * br[j];
        }
    }

    float4 bvec = *reinterpret_cast<const float4*>(bias + colbase + tx * 4);
    float bb[4] = {bvec.x, bvec.y, bvec.z, bvec.w};
    #pragma unroll
    for (int i = 0; i < 4; ++i) {
        int grow = mt * 64 + ty * 4 + i;
        if (grow < cnt) {
            int ridx = g_idx[c * BMAX + grow];
            float4 ov;
            ov.x = fmaxf(accv[i][0] + bb[0], 0.f);
            ov.y = fmaxf(accv[i][1] + bb[1], 0.f);
            ov.z = fmaxf(accv[i][2] + bb[2], 0.f);
            ov.w = fmaxf(accv[i][3] + bb[3], 0.f);
            *reinterpret_cast<float4*>(&g_feature[(size_t)ridx * EDIM + outcol + tx * 4]) = ov;
        }
    }
}

// ---------------------------------------------------------------------------
// classifier: warp per sample, out = sigmoid(feature . Wc + bc)
// ---------------------------------------------------------------------------
__global__ void __launch_bounds__(256) cls_kernel(
    const float* __restrict__ Wc, const float* __restrict__ bc,
    float* __restrict__ out, int B)
{
    const int warp = (blockIdx.x * 256 + threadIdx.x) >> 5;
    const int lane = threadIdx.x & 31;
    if (warp >= B) return;
    const float4* f = reinterpret_cast<const float4*>(g_feature + (size_t)warp * EDIM);
    const float4* wc = reinterpret_cast<const float4*>(Wc);
    float acc = 0.f;
    #pragma unroll
    for (int i = 0; i < 6; ++i) {
        float4 a = f[lane + 32 * i], ww = wc[lane + 32 * i];
        acc += a.x * ww.x + a.y * ww.y + a.z * ww.z + a.w * ww.w;
    }
    #pragma unroll
    for (int o = 16; o; o >>= 1) acc += __shfl_xor_sync(0xffffffffu, acc, o);
    if (lane == 0) out[warp] = 1.f / (1.f + __expf(-(acc + bc[0])));
}

// ---------------------------------------------------------------------------
// domain head stage 2: warp per sample, dp = hdom @ Wdo2 + bdo2 (N=9)
// ---------------------------------------------------------------------------
__global__ void __launch_bounds__(256) domain2_kernel(
    const float* __restrict__ Wdo2, const float* __restrict__ bdo2,
    float* __restrict__ dp, int B)
{
    const int warp = (blockIdx.x * 256 + threadIdx.x) >> 5;
    const int lane = threadIdx.x & 31;
    if (warp >= B) return;
    const float* h = g_hdom + (size_t)warp * HDIM;
    float a[NDOM];
    #pragma unroll
    for (int j = 0; j < NDOM; ++j) a[j] = 0.f;
    #pragma unroll
    for (int i = 0; i < 3; ++i) {
        const int k = (lane + 32 * i) * 4;
        float4 hv = *reinterpret_cast<const float4*>(h + k);
        float hh[4] = {hv.x, hv.y, hv.z, hv.w};
        #pragma unroll
        for (int q = 0; q < 4; ++q) {
            const float* wrow = Wdo2 + (k + q) * NDOM;
            #pragma unroll
            for (int j = 0; j < NDOM; ++j) a[j] += hh[q] * wrow[j];
        }
    }
    #pragma unroll
    for (int j = 0; j < NDOM; ++j) {
        #pragma unroll
        for (int o = 16; o; o >>= 1) a[j] += __shfl_xor_sync(0xffffffffu, a[j], o);
    }
    if (lane == 0) {
        #pragma unroll
        for (int j = 0; j < NDOM; ++j)
            dp[(size_t)warp * NDOM + j] = a[j] + bdo2[j];
    }
}

// ---------------------------------------------------------------------------
extern "C" void kernel_launch(void* const* d_in, const int* in_sizes, int n_in,
                              void* d_out, int out_size)
{
    const float* bert     = (const float*)d_in[0];
    const int*   masks    = (const int*)d_in[1];
    const int*   category = (const int*)d_in[2];
    const float* att_w = (const float*)d_in[4];
    const float* att_b = (const float*)d_in[5];
    const float* Wsh = (const float*)d_in[6];  const float* bsh = (const float*)d_in[7];
    const float* Wsp = (const float*)d_in[8];  const float* bsp = (const float*)d_in[9];
    const float* Wd1 = (const float*)d_in[10]; const float* bd1 = (const float*)d_in[11];
    const float* Wd2 = (const float*)d_in[12]; const float* bd2 = (const float*)d_in[13];
    const float* Wc  = (const float*)d_in[14]; const float* bc  = (const float*)d_in[15];
    const float* Wdo1 = (const float*)d_in[16]; const float* bdo1 = (const float*)d_in[17];
    const float* Wdo2 = (const float*)d_in[18]; const float* bdo2 = (const float*)d_in[19];

    const int B = in_sizes[2];

    float* out    = (float*)d_out;
    float* rec    = out + B;
    float* pooled = rec + (size_t)B * EDIM;
    float* dp     = pooled + (size_t)B * EDIM;

    // TRUE device addresses of the __device__ scratch arrays.
    // (Naming the symbol in host code yields the host shadow address, which on
    // GB300 is ATS-reachable from the GPU and silently corrupts — R2/R3 bug.)
    float *p_feature = nullptr, *p_h1 = nullptr, *p_hdom = nullptr;
    cudaGetSymbolAddress((void**)&p_feature, g_feature);
    cudaGetSymbolAddress((void**)&p_h1, g_h1);
    cudaGetSymbolAddress((void**)&p_hdom, g_hdom);

    // routing lists (off the data critical path)
    zero_counts_kernel<<<1, 16>>>();
    scatter_kernel<<<(B + 255) / 256, 256>>>(category, B);

    pool_kernel<<<B, 192>>>(bert, masks, att_w, att_b, pooled);

    // shared MLP: [B,768]@[768,384] -> g_feature[:, 0:384]
    dense_gemm_relu<<<dim3(HDIM / 64, (B + 63) / 64), 256>>>(
        pooled, EDIM, Wsh, HDIM, bsh, p_feature, EDIM, B, EDIM);

    // specific experts: gathered GEMMs -> g_feature[:, 384:768]
    expert_gemm_kernel<<<dim3(HDIM / 64, (B + 63) / 64, NDOM), 256>>>(pooled, Wsp, bsp);

    // decoder stage 1: [B,768]@[768,64] -> g_h1
    dense_gemm_relu<<<dim3(1, (B + 63) / 64), 256>>>(
        p_feature, EDIM, Wd1, 64, bd1, p_h1, 64, B, EDIM);

    // classifier head
    cls_kernel<<<(B * 32 + 255) / 256, 256>>>(Wc, bc, out, B);

    // domain stage 1: [B,384]@[384,384] -> g_hdom (uses shared = cols 0:384)
    dense_gemm_relu<<<dim3(HDIM / 64, (B + 63) / 64), 256>>>(
        p_feature, EDIM, Wdo1, HDIM, bdo1, p_hdom, HDIM, B, HDIM);

    // domain stage 2
    domain2_kernel<<<(B * 32 + 255) / 256, 256>>>(Wdo2, bdo2, dp, B);

    // decoder stage 2: [B,64]@[64,768] -> rec
    dense_gemm_relu<<<dim3(EDIM / 64, (B + 63) / 64), 256>>>(
        p_h1, 64, Wd2, EDIM, bd2, rec, EDIM, B, 64);
}

// round 5
// speedup vs baseline: 1.4849x; 1.3995x over previous
#include <cuda_runtime.h>
#include <math.h>

#define LSEQ 256
#define EDIM 768
#define HDIM 384
#define NDOM 9
#define BMAX 2048

// device scratch (no allocation allowed)
__device__ float g_feature[(size_t)BMAX * EDIM];   // [B, 2H]: [shared | specific]
__device__ float g_h1[(size_t)BMAX * 64];
__device__ float g_hdom[(size_t)BMAX * HDIM];
__device__ int   g_counts[16];
__device__ int   g_idx[NDOM * BMAX];

// ---------------------------------------------------------------------------
// K1: fused masked-attention pooling, chunked online softmax (8 tokens/iter).
// One CTA / sample, 192 threads, 8 LDG.128 in flight per thread, 1 barrier
// per 8 tokens. Reads bert exactly once (1.61 GB total).
// ---------------------------------------------------------------------------
#define PT 8
__global__ void __launch_bounds__(192) pool_kernel(
    const float* __restrict__ bert, const int* __restrict__ masks,
    const float* __restrict__ att_w, const float* __restrict__ att_b,
    float* __restrict__ pooled)
{
    const int b = blockIdx.x, tid = threadIdx.x;
    const int lane = tid & 31, wid = tid >> 5;
    const float4* base = reinterpret_cast<const float4*>(bert + (size_t)b * LSEQ * EDIM);
    const float4 w = reinterpret_cast<const float4*>(att_w)[tid];
    const float bb = att_b[0];

    __shared__ float wr[2][PT][8];
    __shared__ int msk[LSEQ];
    for (int i = tid; i < LSEQ; i += 192) msk[i] = masks[b * LSEQ + i];

    float4 acc = make_float4(0.f, 0.f, 0.f, 0.f);
    float m = -3e38f, d = 0.f;

    float4 x[PT], xn[PT];
    #pragma unroll
    for (int j = 0; j < PT; ++j) x[j] = base[j * 192 + tid];
    __syncthreads();  // msk ready

    const int NC = LSEQ / PT;
    for (int c = 0; c < NC; ++c) {
        const int cb = c & 1;
        float p[PT];
        #pragma unroll
        for (int j = 0; j < PT; ++j)
            p[j] = x[j].x * w.x + x[j].y * w.y + x[j].z * w.z + x[j].w * w.w;

        if (c + 1 < NC) {
            #pragma unroll
            for (int j = 0; j < PT; ++j)
                xn[j] = base[((c + 1) * PT + j) * 192 + tid];
        }

        #pragma unroll
        for (int j = 0; j < PT; ++j) {
            #pragma unroll
            for (int o = 16; o; o >>= 1)
                p[j] += __shfl_xor_sync(0xffffffffu, p[j], o);
        }
        if (lane == 0) {
            #pragma unroll
            for (int j = 0; j < PT; ++j) wr[cb][j][wid] = p[j];
        }
        __syncthreads();

        float s[PT], Mc = -3e38f;
        #pragma unroll
        for (int j = 0; j < PT; ++j) {
            s[j] = wr[cb][j][0] + wr[cb][j][1] + wr[cb][j][2]
                 + wr[cb][j][3] + wr[cb][j][4] + wr[cb][j][5] + bb;
            if (msk[c * PT + j] == 0) s[j] = -1e9f;
            Mc = fmaxf(Mc, s[j]);
        }
        float pe[PT], dc = 0.f;
        #pragma unroll
        for (int j = 0; j < PT; ++j) { pe[j] = __expf(s[j] - Mc); dc += pe[j]; }
        float4 ca = make_float4(0.f, 0.f, 0.f, 0.f);
        #pragma unroll
        for (int j = 0; j < PT; ++j) {
            ca.x += pe[j] * x[j].x; ca.y += pe[j] * x[j].y;
            ca.z += pe[j] * x[j].z; ca.w += pe[j] * x[j].w;
        }
        const float nm = fmaxf(m, Mc);
        const float fo = __expf(m - nm), fn = __expf(Mc - nm);
        d = d * fo + dc * fn;
        acc.x = acc.x * fo + ca.x * fn;
        acc.y = acc.y * fo + ca.y * fn;
        acc.z = acc.z * fo + ca.z * fn;
        acc.w = acc.w * fo + ca.w * fn;
        m = nm;
        #pragma unroll
        for (int j = 0; j < PT; ++j) x[j] = xn[j];
    }
    const float inv = 1.f / d;
    float4 o = make_float4(acc.x * inv, acc.y * inv, acc.z * inv, acc.w * inv);
    reinterpret_cast<float4*>(pooled + (size_t)b * EDIM)[tid] = o;
}

// ---------------------------------------------------------------------------
// category routing lists
// ---------------------------------------------------------------------------
__global__ void zero_counts_kernel() { if (threadIdx.x < 16) g_counts[threadIdx.x] = 0; }

__global__ void scatter_kernel(const int* __restrict__ category, int B) {
    int i = blockIdx.x * blockDim.x + threadIdx.x;
    if (i < B) {
        int c = category[i];
        int p = atomicAdd(&g_counts[c], 1);
        g_idx[c * BMAX + p] = i;
    }
}

// ---------------------------------------------------------------------------
// Dense tiled GEMM, double-buffered: C = relu(A @ W + bias).
// Tile (16*MM) x 64, K-step 16, 256 threads, ONE __syncthreads per K-step,
// next tile prefetched to registers during compute. K%16==0, N%64==0.
// ---------------------------------------------------------------------------
template<int MM>
__global__ void __launch_bounds__(256) gemm_bias_relu(
    const float* __restrict__ A, int lda,
    const float* __restrict__ W, int ldw,
    const float* __restrict__ bias,
    float* __restrict__ C, int ldc,
    int M, int K)
{
    constexpr int BM = 16 * MM;
    constexpr int APAD = BM + 4;
    const int mt = blockIdx.y;
    const int colbase = blockIdx.x * 64;

    __shared__ float As[2][16][APAD];
    __shared__ float Bs[2][16][64];

    const int t = threadIdx.x;
    const int arow = t >> 2, akk = (t & 3) * 4;
    const int bk = t >> 4, bn = (t & 15) * 4;
    const int ty = t >> 4, tx = t & 15;

    const int ga = mt * BM + arow;
    const bool aload = (arow < BM) && (ga < M);
    const float* Ap = A + (size_t)(aload ? ga : 0) * lda;

    float acc[MM][4];
    #pragma unroll
    for (int i = 0; i < MM; ++i)
        #pragma unroll
        for (int j = 0; j < 4; ++j) acc[i][j] = 0.f;

    const int NS = K / 16;
    float4 av = make_float4(0.f, 0.f, 0.f, 0.f);
    if (aload) av = *reinterpret_cast<const float4*>(Ap + akk);
    float4 bv = *reinterpret_cast<const float4*>(W + (size_t)bk * ldw + colbase + bn);
    if (arow < BM) {
        As[0][akk + 0][arow] = av.x; As[0][akk + 1][arow] = av.y;
        As[0][akk + 2][arow] = av.z; As[0][akk + 3][arow] = av.w;
    }
    *reinterpret_cast<float4*>(&Bs[0][bk][bn]) = bv;
    __syncthreads();

    for (int s = 0; s < NS; ++s) {
        const int cur = s & 1;
        float4 av2 = make_float4(0.f, 0.f, 0.f, 0.f), bv2;
        if (s + 1 < NS) {
            const int k0 = (s + 1) * 16;
            if (aload) av2 = *reinterpret_cast<const float4*>(Ap + k0 + akk);
            bv2 = *reinterpret_cast<const float4*>(W + (size_t)(k0 + bk) * ldw + colbase + bn);
        }
        #pragma unroll
        for (int kk = 0; kk < 16; ++kk) {
            float a[MM];
            if constexpr (MM == 4) {
                float4 a4 = *reinterpret_cast<const float4*>(&As[cur][kk][ty * 4]);
                a[0] = a4.x; a[1] = a4.y; a[2] = a4.z; a[3] = a4.w;
            } else {
                #pragma unroll
                for (int i = 0; i < MM; ++i) a[i] = As[cur][kk][ty * MM + i];
            }
            float4 b4 = *reinterpret_cast<const float4*>(&Bs[cur][kk][tx * 4]);
            float br[4] = {b4.x, b4.y, b4.z, b4.w};
            #pragma unroll
            for (int i = 0; i < MM; ++i)
                #pragma unroll
                for (int j = 0; j < 4; ++j) acc[i][j] += a[i] * br[j];
        }
        if (s + 1 < NS) {
            const int nb = cur ^ 1;
            if (arow < BM) {
                As[nb][akk + 0][arow] = av2.x; As[nb][akk + 1][arow] = av2.y;
                As[nb][akk + 2][arow] = av2.z; As[nb][akk + 3][arow] = av2.w;
            }
            *reinterpret_cast<float4*>(&Bs[nb][bk][bn]) = bv2;
        }
        __syncthreads();
    }

    float4 bb4 = *reinterpret_cast<const float4*>(bias + colbase + tx * 4);
    float bb[4] = {bb4.x, bb4.y, bb4.z, bb4.w};
    #pragma unroll
    for (int i = 0; i < MM; ++i) {
        const int row = mt * BM + ty * MM + i;
        if (row < M) {
            float4 o;
            o.x = fmaxf(acc[i][0] + bb[0], 0.f);
            o.y = fmaxf(acc[i][1] + bb[1], 0.f);
            o.z = fmaxf(acc[i][2] + bb[2], 0.f);
            o.w = fmaxf(acc[i][3] + bb[3], 0.f);
            *reinterpret_cast<float4*>(C + (size_t)row * ldc + colbase + tx * 4) = o;
        }
    }
}

// ---------------------------------------------------------------------------
// Fused expert + shared GEMM, double-buffered. blockIdx.z: 0..8 = gathered
// specific expert (out cols [H,2H)), 9 = dense shared MLP (out cols [0,H)).
// ---------------------------------------------------------------------------
__global__ void __launch_bounds__(256) expert_gemm_kernel(
    const float* __restrict__ pooled,
    const float* __restrict__ Wsh, const float* __restrict__ bsh,
    const float* __restrict__ Wsp, const float* __restrict__ bsp,
    int B)
{
    const int c = blockIdx.z;
    const bool dense = (c == NDOM);
    const int cnt = dense ? B : g_counts[c];
    const int mt = blockIdx.y;
    if (mt * 64 >= cnt) return;

    const float* W    = dense ? Wsh : (Wsp + (size_t)c * EDIM * HDIM);
    const float* bias = dense ? bsh : (bsp + c * HDIM);
    const int colbase = blockIdx.x * 64;
    const int outcol  = (dense ? 0 : HDIM) + colbase;

    __shared__ float As[2][16][68];
    __shared__ float Bs[2][16][64];

    const int t = threadIdx.x;
    const int arow = t >> 2, akk = (t & 3) * 4;
    const int bk = t >> 4, bn = (t & 15) * 4;
    const int ty = t >> 4, tx = t & 15;

    int gi = -1;
    {
        const int amrow = mt * 64 + arow;
        if (amrow < cnt) gi = dense ? amrow : g_idx[c * BMAX + amrow];
    }
    const float* Ap = pooled + (size_t)(gi >= 0 ? gi : 0) * EDIM;

    float acc[4][4];
    #pragma unroll
    for (int i = 0; i < 4; ++i)
        #pragma unroll
        for (int j = 0; j < 4; ++j) acc[i][j] = 0.f;

    const int NS = EDIM / 16;
    float4 av = make_float4(0.f, 0.f, 0.f, 0.f);
    if (gi >= 0) av = *reinterpret_cast<const float4*>(Ap + akk);
    float4 bv = *reinterpret_cast<const float4*>(W + (size_t)bk * HDIM + colbase + bn);
    As[0][akk + 0][arow] = av.x; As[0][akk + 1][arow] = av.y;
    As[0][akk + 2][arow] = av.z; As[0][akk + 3][arow] = av.w;
    *reinterpret_cast<float4*>(&Bs[0][bk][bn]) = bv;
    __syncthreads();

    for (int s = 0; s < NS; ++s) {
        const int cur = s & 1;
        float4 av2 = make_float4(0.f, 0.f, 0.f, 0.f), bv2;
        if (s + 1 < NS) {
            const int k0 = (s + 1) * 16;
            if (gi >= 0) av2 = *reinterpret_cast<const float4*>(Ap + k0 + akk);
            bv2 = *reinterpret_cast<const float4*>(W + (size_t)(k0 + bk) * HDIM + colbase + bn);
        }
        #pragma unroll
        for (int kk = 0; kk < 16; ++kk) {
            float4 a4 = *reinterpret_cast<const float4*>(&As[cur][kk][ty * 4]);
            float4 b4 = *reinterpret_cast<const float4*>(&Bs[cur][kk][tx * 4]);
            float ar[4] = {a4.x, a4.y, a4.z, a4.w};
            float br[4] = {b4.x, b4.y, b4.z, b4.w};
            #pragma unroll
            for (int i = 0; i < 4; ++i)
                #pragma unroll
                for (int j = 0; j < 4; ++j) acc[i][j] += ar[i] * br[j];
        }
        if (s + 1 < NS) {
            const int nb = cur ^ 1;
            As[nb][akk + 0][arow] = av2.x; As[nb][akk + 1][arow] = av2.y;
            As[nb][akk + 2][arow] = av2.z; As[nb][akk + 3][arow] = av2.w;
            *reinterpret_cast<float4*>(&Bs[nb][bk][bn]) = bv2;
        }
        __syncthreads();
    }

    float4 bb4 = *reinterpret_cast<const float4*>(bias + colbase + tx * 4);
    float bb[4] = {bb4.x, bb4.y, bb4.z, bb4.w};
    #pragma unroll
    for (int i = 0; i < 4; ++i) {
        const int grow = mt * 64 + ty * 4 + i;
        if (grow < cnt) {
            const int ridx = dense ? grow : g_idx[c * BMAX + grow];
            float4 o;
            o.x = fmaxf(acc[i][0] + bb[0], 0.f);
            o.y = fmaxf(acc[i][1] + bb[1], 0.f);
            o.z = fmaxf(acc[i][2] + bb[2], 0.f);
            o.w = fmaxf(acc[i][3] + bb[3], 0.f);
            *reinterpret_cast<float4*>(&g_feature[(size_t)ridx * EDIM + outcol + tx * 4]) = o;
        }
    }
}

// ---------------------------------------------------------------------------
// classifier: warp per sample, out = sigmoid(feature . Wc + bc)
// ---------------------------------------------------------------------------
__global__ void __launch_bounds__(256) cls_kernel(
    const float* __restrict__ Wc, const float* __restrict__ bc,
    float* __restrict__ out, int B)
{
    const int warp = (blockIdx.x * 256 + threadIdx.x) >> 5;
    const int lane = threadIdx.x & 31;
    if (warp >= B) return;
    const float4* f = reinterpret_cast<const float4*>(g_feature + (size_t)warp * EDIM);
    const float4* wc = reinterpret_cast<const float4*>(Wc);
    float acc = 0.f;
    #pragma unroll
    for (int i = 0; i < 6; ++i) {
        float4 a = f[lane + 32 * i], ww = wc[lane + 32 * i];
        acc += a.x * ww.x + a.y * ww.y + a.z * ww.z + a.w * ww.w;
    }
    #pragma unroll
    for (int o = 16; o; o >>= 1) acc += __shfl_xor_sync(0xffffffffu, acc, o);
    if (lane == 0) out[warp] = 1.f / (1.f + __expf(-(acc + bc[0])));
}

// ---------------------------------------------------------------------------
// domain head stage 2: warp per sample, dp = hdom @ Wdo2 + bdo2 (N=9)
// ---------------------------------------------------------------------------
__global__ void __launch_bounds__(256) domain2_kernel(
    const float* __restrict__ Wdo2, const float* __restrict__ bdo2,
    float* __restrict__ dp, int B)
{
    const int warp = (blockIdx.x * 256 + threadIdx.x) >> 5;
    const int lane = threadIdx.x & 31;
    if (warp >= B) return;
    const float* h = g_hdom + (size_t)warp * HDIM;
    float a[NDOM];
    #pragma unroll
    for (int j = 0; j < NDOM; ++j) a[j] = 0.f;
    #pragma unroll
    for (int i = 0; i < 3; ++i) {
        const int k = (lane + 32 * i) * 4;
        float4 hv = *reinterpret_cast<const float4*>(h + k);
        float hh[4] = {hv.x, hv.y, hv.z, hv.w};
        #pragma unroll
        for (int q = 0; q < 4; ++q) {
            const float* wrow = Wdo2 + (k + q) * NDOM;
            #pragma unroll
            for (int j = 0; j < NDOM; ++j) a[j] += hh[q] * wrow[j];
        }
    }
    #pragma unroll
    for (int j = 0; j < NDOM; ++j) {
        #pragma unroll
        for (int o = 16; o; o >>= 1) a[j] += __shfl_xor_sync(0xffffffffu, a[j], o);
    }
    if (lane == 0) {
        #pragma unroll
        for (int j = 0; j < NDOM; ++j)
            dp[(size_t)warp * NDOM + j] = a[j] + bdo2[j];
    }
}

// ---------------------------------------------------------------------------
extern "C" void kernel_launch(void* const* d_in, const int* in_sizes, int n_in,
                              void* d_out, int out_size)
{
    const float* bert     = (const float*)d_in[0];
    const int*   masks    = (const int*)d_in[1];
    const int*   category = (const int*)d_in[2];
    const float* att_w = (const float*)d_in[4];
    const float* att_b = (const float*)d_in[5];
    const float* Wsh = (const float*)d_in[6];  const float* bsh = (const float*)d_in[7];
    const float* Wsp = (const float*)d_in[8];  const float* bsp = (const float*)d_in[9];
    const float* Wd1 = (const float*)d_in[10]; const float* bd1 = (const float*)d_in[11];
    const float* Wd2 = (const float*)d_in[12]; const float* bd2 = (const float*)d_in[13];
    const float* Wc  = (const float*)d_in[14]; const float* bc  = (const float*)d_in[15];
    const float* Wdo1 = (const float*)d_in[16]; const float* bdo1 = (const float*)d_in[17];
    const float* Wdo2 = (const float*)d_in[18]; const float* bdo2 = (const float*)d_in[19];

    const int B = in_sizes[2];

    float* out    = (float*)d_out;
    float* rec    = out + B;
    float* pooled = rec + (size_t)B * EDIM;
    float* dp     = pooled + (size_t)B * EDIM;

    // TRUE device addresses of __device__ scratch (host shadow address is
    // ATS-reachable on GB300 and silently corrupts — R2/R3 lesson).
    float *p_feature = nullptr, *p_h1 = nullptr, *p_hdom = nullptr;
    cudaGetSymbolAddress((void**)&p_feature, g_feature);
    cudaGetSymbolAddress((void**)&p_h1, g_h1);
    cudaGetSymbolAddress((void**)&p_hdom, g_hdom);

    // routing lists (off the data critical path)
    zero_counts_kernel<<<1, 16>>>();
    scatter_kernel<<<(B + 255) / 256, 256>>>(category, B);

    pool_kernel<<<B, 192>>>(bert, masks, att_w, att_b, pooled);

    // shared MLP (slab 9) + 9 specific experts in one launch
    expert_gemm_kernel<<<dim3(HDIM / 64, (B + 63) / 64, NDOM + 1), 256>>>(
        pooled, Wsh, bsh, Wsp, bsp, B);

    // decoder stage 1: [B,768]@[768,64] -> g_h1  (BM=16 -> 128 CTAs)
    gemm_bias_relu<1><<<dim3(1, (B + 15) / 16), 256>>>(
        p_feature, EDIM, Wd1, 64, bd1, p_h1, 64, B, EDIM);

    // domain stage 1: [B,384]@[384,384] -> g_hdom (shared = cols 0:384)
    gemm_bias_relu<4><<<dim3(HDIM / 64, (B + 63) / 64), 256>>>(
        p_feature, EDIM, Wdo1, HDIM, bdo1, p_hdom, HDIM, B, HDIM);

    // classifier head
    cls_kernel<<<(B * 32 + 255) / 256, 256>>>(Wc, bc, out, B);

    // domain stage 2
    domain2_kernel<<<(B * 32 + 255) / 256, 256>>>(Wdo2, bdo2, dp, B);

    // decoder stage 2: [B,64]@[64,768] -> rec
    gemm_bias_relu<4><<<dim3(EDIM / 64, (B + 63) / 64), 256>>>(
        p_h1, 64, Wd2, EDIM, bd2, rec, EDIM, B, 64);
}